// round 14
// baseline (speedup 1.0000x reference)
#include <cuda_runtime.h>
#include <cuda_fp16.h>
#include <cstdint>

// ---------------- problem constants ----------------
#define Nn_NODES 16384      // B*L
#define Dm 256              // d_model
#define Hh 4                // heads
#define Cc 256              // per-head channels
#define HD (Hh*Cc)          // 1024
#define Ee 65536            // edges
#define NEG_SLOPE 0.2f
#define LN_EPS 1e-6f

// ---------------- device scratch ----------------
// A-side operands: fp16 hi/lo split. B-side operands: single fp16.
__device__ __half g_xln_hi[Nn_NODES * Dm];
__device__ __half g_xln_lo[Nn_NODES * Dm];
__device__ __half g_agg_hi[Nn_NODES * Dm];
__device__ __half g_agg_lo[Nn_NODES * Dm];
__device__ __half g_wg_hi[HD * Dm], g_wg_lo[HD * Dm];   // Wgat (A of w12 GEMM)
__device__ __half g_w1t [Dm * Dm];                      // W1^T (B, single)
__device__ __half g_w2  [Dm * Dm];                      // W2   (B, single)
__device__ __half g_w12 [HD * Dm];                      // Wgat@W1 (B, single)
__device__ float  g_c12 [HD];                           // Wgat @ b1
__device__ __half g_xh  [Nn_NODES * HD];                // fp16 (halved gather traffic)
__device__ float  g_asrc[Nn_NODES * Hh];
__device__ float  g_adst[Nn_NODES * Hh];
// CSR structures
__device__ int g_deg   [Nn_NODES];
__device__ int g_offs  [Nn_NODES];
__device__ int g_cursor[Nn_NODES];
__device__ int g_csr_src[Ee];

// ---------------- helpers ----------------
__device__ __forceinline__ float leaky(float x) { return x > 0.0f ? x : NEG_SLOPE * x; }
__device__ __forceinline__ unsigned f2o(float f) {
    unsigned u = __float_as_uint(f);
    return (u & 0x80000000u) ? ~u : (u | 0x80000000u);
}
__device__ __forceinline__ float o2f(unsigned u) {
    return (u & 0x80000000u) ? __uint_as_float(u & 0x7FFFFFFFu) : __uint_as_float(~u);
}
__device__ __forceinline__ float warp_sum(float v) {
    #pragma unroll
    for (int o = 16; o > 0; o >>= 1) v += __shfl_xor_sync(0xFFFFFFFFu, v, o);
    return v;
}
__device__ __forceinline__ void split2h(float v, __half& h, __half& l) {
    h = __float2half(v);
    l = __float2half(v - __half2float(h));
}
__device__ __forceinline__ uint32_t smem_to_u32(const void* p) {
    uint32_t a;
    asm("{ .reg .u64 t; cvta.to.shared.u64 t, %1; cvt.u32.u64 %0, t; }"
        : "=r"(a) : "l"(p));
    return a;
}

// ---------------- mma / ldmatrix / cp.async PTX (sm_80-compatible) --------
#define LDM4(r, addr) \
    asm volatile("ldmatrix.sync.aligned.m8n8.x4.shared.b16 {%0,%1,%2,%3}, [%4];" \
        : "=r"((r)[0]), "=r"((r)[1]), "=r"((r)[2]), "=r"((r)[3]) : "r"(addr))

#define MMA_F16(c, a, b0, b1) \
    asm volatile("mma.sync.aligned.m16n8k16.row.col.f32.f16.f16.f32 " \
        "{%0,%1,%2,%3}, {%4,%5,%6,%7}, {%8,%9}, {%0,%1,%2,%3};" \
        : "+f"((c)[0]), "+f"((c)[1]), "+f"((c)[2]), "+f"((c)[3]) \
        : "r"((a)[0]), "r"((a)[1]), "r"((a)[2]), "r"((a)[3]), "r"(b0), "r"(b1))

#define CP_ASYNC16(dst, src) \
    asm volatile("cp.async.cg.shared.global [%0], [%1], 16;" \
        :: "r"(dst), "l"(src) : "memory")
#define CP_COMMIT() asm volatile("cp.async.commit_group;" ::: "memory")
#define CP_WAIT1()  asm volatile("cp.async.wait_group 1;" ::: "memory")
#define CP_WAIT0()  asm volatile("cp.async.wait_group 0;" ::: "memory")

// ---------------- K0: weight prep + c12 + zero init ----------------
__global__ __launch_bounds__(256) void splitW_kernel(
    const float* __restrict__ W1, const float* __restrict__ Wg,
    const float* __restrict__ W2, const float* __restrict__ b1)
{
    int i = blockIdx.x * 256 + threadIdx.x;     // grid covers HD*Dm = 262144
    if (i < Dm * Dm) {
        int k = i >> 8, n = i & 255;
        g_w1t[n * 256 + k] = __float2half(W1[i]);   // transposed, single fp16
        g_w2[i] = __float2half(W2[i]);
    }
    split2h(Wg[i], g_wg_hi[i], g_wg_lo[i]);
    if (i < Nn_NODES) { g_deg[i] = 0; g_cursor[i] = 0; }
    if (i < Nn_NODES * Hh) { g_asrc[i] = 0.f; g_adst[i] = 0.f; }

    // c12 = Wgat @ b1 : first 128 blocks, one warp per output row
    if (blockIdx.x < 128) {
        int w = threadIdx.x >> 5, lane = threadIdx.x & 31;
        int j = blockIdx.x * 8 + w;
        float acc = 0.f;
        #pragma unroll
        for (int c = 0; c < 8; c++)
            acc = fmaf(Wg[(size_t)j * 256 + lane + c * 32], b1[lane + c * 32], acc);
        acc = warp_sum(acc);
        if (lane == 0) g_c12[j] = acc;
    }
}

// ---------------- K1: LayerNorm (warp/row) + edge histogram (fused) -------
__global__ __launch_bounds__(256) void ln_hist_kernel(
    const float* __restrict__ x, const float* __restrict__ gamma,
    const float* __restrict__ beta, const int* __restrict__ edst)
{
    if (blockIdx.x < Ee / 256) {
        int e = blockIdx.x * 256 + threadIdx.x;
        atomicAdd(&g_deg[edst[e]], 1);
    }

    int row  = blockIdx.x * 8 + (threadIdx.x >> 5);
    int lane = threadIdx.x & 31;
    const float* xr = x + (size_t)row * Dm;
    float4 v0 = *(const float4*)(xr + lane * 4);
    float4 v1 = *(const float4*)(xr + 128 + lane * 4);
    float s  = v0.x + v0.y + v0.z + v0.w + v1.x + v1.y + v1.z + v1.w;
    float s2 = v0.x*v0.x + v0.y*v0.y + v0.z*v0.z + v0.w*v0.w
             + v1.x*v1.x + v1.y*v1.y + v1.z*v1.z + v1.w*v1.w;
    s = warp_sum(s);
    s2 = warp_sum(s2);
    float mu   = s * (1.0f / Dm);
    float var  = s2 * (1.0f / Dm) - mu * mu;
    float rstd = rsqrtf(var + LN_EPS);

    float o[8];
    float4 gm0 = *(const float4*)(gamma + lane * 4);
    float4 gm1 = *(const float4*)(gamma + 128 + lane * 4);
    float4 bt0 = *(const float4*)(beta + lane * 4);
    float4 bt1 = *(const float4*)(beta + 128 + lane * 4);
    o[0] = (v0.x - mu) * rstd * gm0.x + bt0.x;
    o[1] = (v0.y - mu) * rstd * gm0.y + bt0.y;
    o[2] = (v0.z - mu) * rstd * gm0.z + bt0.z;
    o[3] = (v0.w - mu) * rstd * gm0.w + bt0.w;
    o[4] = (v1.x - mu) * rstd * gm1.x + bt1.x;
    o[5] = (v1.y - mu) * rstd * gm1.y + bt1.y;
    o[6] = (v1.z - mu) * rstd * gm1.z + bt1.z;
    o[7] = (v1.w - mu) * rstd * gm1.w + bt1.w;
    #pragma unroll
    for (int i = 0; i < 8; i++) {
        size_t idx = (size_t)row * Dm + (i < 4 ? lane * 4 + i : 128 + lane * 4 + i - 4);
        split2h(o[i], g_xln_hi[idx], g_xln_lo[idx]);
    }
}

// ---------------- fp16x2 HMMA GEMM: C = (Ahi+Alo) @ B^T, 2 passes ---------
#define ST_STRIDE 32768
#define O_B 16384
#define GEMM_SMEM (3 * ST_STRIDE)

__global__ __launch_bounds__(256, 2) void gemm_mma(
    const __half* __restrict__ Ahi, const __half* __restrict__ Alo,
    const __half* __restrict__ B,
    int Ncols, const float* __restrict__ c_bias, const float* __restrict__ resid,
    float* __restrict__ Cf32,
    __half* __restrict__ Chi, __half* __restrict__ Clo,   // A-split output
    __half* __restrict__ Cone,                            // single-fp16 output
    const float* __restrict__ att_s, const float* __restrict__ att_d)
{
    extern __shared__ char smem[];
    uint32_t sb = smem_to_u32(smem);
    const int tid = threadIdx.x, lane = tid & 31, wid = tid >> 5;
    const int warp_m0 = (wid >> 2) * 64;
    const int warp_n0 = (wid & 3) * 32;
    const size_t m0 = (size_t)blockIdx.y * 128;
    const size_t n0 = (size_t)blockIdx.x * 128;

    float acc[4][4][4];
    #pragma unroll
    for (int i = 0; i < 4; i++)
        #pragma unroll
        for (int j = 0; j < 4; j++)
            #pragma unroll
            for (int k = 0; k < 4; k++) acc[i][j][k] = 0.f;

    const int arow = lane & 15;
    const int akb  = (lane >> 4) << 4;
    const int brl  = ((lane >> 4) << 3) | (lane & 7);
    const int bkb  = ((lane >> 3) & 1) << 4;
    const uint32_t aswz = (uint32_t)(arow & 7) << 4;
    const uint32_t bswz = (uint32_t)(lane & 7) << 4;

    auto issue = [&](int stage, int chunk) {
        int p   = chunk >> 2;                    // 0: Ahi, 1: Alo
        int kc0 = (chunk & 3) * 64;
        const __half* Ap = p ? Alo : Ahi;
        uint32_t s0 = sb + stage * ST_STRIDE;
        #pragma unroll
        for (int it = 0; it < 4; ++it) {
            int idx = tid + it * 256;
            int row = idx >> 3, c16 = idx & 7;
            uint32_t off = (uint32_t)row * 128 + c16 * 16;
            off ^= ((uint32_t)(row & 7)) << 4;           // SW128
            CP_ASYNC16(s0 + off,       Ap + (m0 + row) * 256 + kc0 + c16 * 8);
            CP_ASYNC16(s0 + O_B + off, B  + (n0 + row) * 256 + kc0 + c16 * 8);
        }
    };

    auto ldfrag = [&](uint32_t st, int k16, uint32_t af[4][4], uint32_t bf[2][4]) {
        int kbyte = k16 * 32;
        #pragma unroll
        for (int mt = 0; mt < 4; ++mt) {
            uint32_t ad = st +
                (uint32_t)(warp_m0 + mt * 16 + arow) * 128 + kbyte + akb;
            LDM4(af[mt], ad ^ aswz);
        }
        #pragma unroll
        for (int g2 = 0; g2 < 2; ++g2) {
            uint32_t bd = st + O_B +
                (uint32_t)(warp_n0 + g2 * 16 + brl) * 128 + kbyte + bkb;
            LDM4(bf[g2], bd ^ bswz);
        }
    };

    issue(0, 0); CP_COMMIT();
    issue(1, 1); CP_COMMIT();

    uint32_t af[2][4][4], bf[2][2][4];

    for (int c = 0; c < 8; ++c) {
        if (c < 7) { CP_WAIT1(); } else { CP_WAIT0(); }
        __syncthreads();
        if (c + 2 < 8) { issue((c + 2) % 3, c + 2); CP_COMMIT(); }

        uint32_t st = sb + (c % 3) * ST_STRIDE;
        ldfrag(st, 0, af[0], bf[0]);
        #pragma unroll
        for (int k16 = 0; k16 < 4; ++k16) {
            int cur = k16 & 1, nxt = cur ^ 1;
            if (k16 < 3) ldfrag(st, k16 + 1, af[nxt], bf[nxt]);
            #pragma unroll
            for (int mt = 0; mt < 4; ++mt)
                #pragma unroll
                for (int nt = 0; nt < 4; ++nt) {
                    int g2 = nt >> 1, p2 = (nt & 1) << 1;
                    MMA_F16(acc[mt][nt], af[cur][mt], bf[cur][g2][p2],
                            bf[cur][g2][p2 + 1]);
                }
        }
    }
    __syncthreads();

    // ---- epilogue ----
    const int g = lane >> 2, tq = lane & 3;

    const int h_att = (int)(n0 >> 8);
    float as0[4], as1[4], ad0[4], ad1[4];
    float ps[4][2], pd[4][2];
    if (att_s) {
        int cih0 = (int)(n0 & 255) + warp_n0 + tq * 2;
        #pragma unroll
        for (int nt = 0; nt < 4; ++nt) {
            int cih = cih0 + nt * 8;
            as0[nt] = att_s[h_att * Cc + cih];
            as1[nt] = att_s[h_att * Cc + cih + 1];
            ad0[nt] = att_d[h_att * Cc + cih];
            ad1[nt] = att_d[h_att * Cc + cih + 1];
        }
        #pragma unroll
        for (int mt = 0; mt < 4; ++mt)
            #pragma unroll
            for (int rh = 0; rh < 2; ++rh) { ps[mt][rh] = 0.f; pd[mt][rh] = 0.f; }
    }

    #pragma unroll
    for (int mt = 0; mt < 4; ++mt) {
        #pragma unroll
        for (int nt = 0; nt < 4; ++nt) {
            size_t r = m0 + warp_m0 + mt * 16 + g;
            size_t c = n0 + warp_n0 + nt * 8 + tq * 2;
            float v00 = acc[mt][nt][0], v01 = acc[mt][nt][1];
            float v10 = acc[mt][nt][2], v11 = acc[mt][nt][3];
            if (c_bias) {
                float cb0 = c_bias[c], cb1 = c_bias[c + 1];
                v00 += cb0; v01 += cb1; v10 += cb0; v11 += cb1;
            }
            size_t o0 = r * (size_t)Ncols + c;
            size_t o1 = (r + 8) * (size_t)Ncols + c;
            if (resid) {
                v00 += resid[o0]; v01 += resid[o0 + 1];
                v10 += resid[o1]; v11 += resid[o1 + 1];
            }
            if (att_s) {
                ps[mt][0] = fmaf(v00, as0[nt], fmaf(v01, as1[nt], ps[mt][0]));
                pd[mt][0] = fmaf(v00, ad0[nt], fmaf(v01, ad1[nt], pd[mt][0]));
                ps[mt][1] = fmaf(v10, as0[nt], fmaf(v11, as1[nt], ps[mt][1]));
                pd[mt][1] = fmaf(v10, ad0[nt], fmaf(v11, ad1[nt], pd[mt][1]));
            }
            if (Cf32) {
                *(float2*)(Cf32 + o0) = make_float2(v00, v01);
                *(float2*)(Cf32 + o1) = make_float2(v10, v11);
            }
            if (Chi) {
                split2h(v00, Chi[o0], Clo[o0]);
                split2h(v01, Chi[o0 + 1], Clo[o0 + 1]);
                split2h(v10, Chi[o1], Clo[o1]);
                split2h(v11, Chi[o1 + 1], Clo[o1 + 1]);
            }
            if (Cone) {
                Cone[o0] = __float2half(v00);
                Cone[o0 + 1] = __float2half(v01);
                Cone[o1] = __float2half(v10);
                Cone[o1 + 1] = __float2half(v11);
            }
        }
    }

    if (att_s) {
        #pragma unroll
        for (int mt = 0; mt < 4; ++mt)
            #pragma unroll
            for (int rh = 0; rh < 2; ++rh) {
                float vs = ps[mt][rh], vd = pd[mt][rh];
                vs += __shfl_xor_sync(0xFFFFFFFFu, vs, 1);
                vs += __shfl_xor_sync(0xFFFFFFFFu, vs, 2);
                vd += __shfl_xor_sync(0xFFFFFFFFu, vd, 1);
                vd += __shfl_xor_sync(0xFFFFFFFFu, vd, 2);
                if (tq == 0) {
                    size_t r = m0 + warp_m0 + mt * 16 + g + rh * 8;
                    atomicAdd(&g_asrc[r * Hh + h_att], vs);
                    atomicAdd(&g_adst[r * Hh + h_att], vd);
                }
            }
    }
}

// ---------------- scan: 1 block, int4 vectorized ----------------
__global__ __launch_bounds__(1024) void scan_kernel() {
    __shared__ int sh[2][1024];
    int t = threadIdx.x;
    const int4* d4 = (const int4*)g_deg;
    int4 v4[4];
    #pragma unroll
    for (int i = 0; i < 4; i++) v4[i] = d4[t * 4 + i];
    int v[16];
    #pragma unroll
    for (int i = 0; i < 4; i++) {
        v[i*4+0] = ((const int*)&v4[i])[0];
        v[i*4+1] = ((const int*)&v4[i])[1];
        v[i*4+2] = ((const int*)&v4[i])[2];
        v[i*4+3] = ((const int*)&v4[i])[3];
    }
    int sum = 0;
    #pragma unroll
    for (int i = 0; i < 16; i++) sum += v[i];
    sh[0][t] = sum;
    __syncthreads();
    int p = 0;
    #pragma unroll
    for (int off = 1; off < 1024; off <<= 1) {
        int val = sh[p][t] + ((t >= off) ? sh[p][t - off] : 0);
        sh[p ^ 1][t] = val;
        p ^= 1;
        __syncthreads();
    }
    int run = sh[p][t] - sum;
    int4 o4[4];
    #pragma unroll
    for (int i = 0; i < 4; i++) {
        ((int*)&o4[i])[0] = run; run += v[i*4+0];
        ((int*)&o4[i])[1] = run; run += v[i*4+1];
        ((int*)&o4[i])[2] = run; run += v[i*4+2];
        ((int*)&o4[i])[3] = run; run += v[i*4+3];
    }
    int4* out4 = (int4*)g_offs;
    #pragma unroll
    for (int i = 0; i < 4; i++) out4[t * 4 + i] = o4[i];
}

__global__ __launch_bounds__(256) void scatter_kernel(
    const int* __restrict__ esrc, const int* __restrict__ edst)
{
    int e = blockIdx.x * 256 + threadIdx.x;
    int d = edst[e];
    int pos = g_offs[d] + atomicAdd(&g_cursor[d], 1);
    g_csr_src[pos] = esrc[e];
}

// ---------------- fused node softmax + aggregation (fp16 xh gathers) -----
#define MAXCH 64
__global__ __launch_bounds__(256) void node_agg_kernel(
    const float* __restrict__ bias_gat)
{
    int n = blockIdx.x, t = threadIdx.x;
    int start = g_offs[n], dcount = g_deg[n];

    __shared__ unsigned s_max[Hh];
    __shared__ float s_den[Hh];
    __shared__ float s_adst[Hh], s_self[Hh], s_wself[Hh];
    __shared__ float s_w[MAXCH][Hh];
    __shared__ int s_src[MAXCH];

    if (t < Hh) {
        float as = g_asrc[n * Hh + t], ad = g_adst[n * Hh + t];
        s_adst[t] = ad;
        float self = leaky(as + ad);
        s_self[t] = self;
        s_max[t] = f2o(self);
        s_den[t] = 0.f;
    }
    __syncthreads();

    int et = t >> 2, h = t & 3;
    int cnt0 = min(dcount, MAXCH);

    if (et < cnt0) {
        int s = g_csr_src[start + et];
        float logit = leaky(g_asrc[s * Hh + h] + s_adst[h]);
        s_w[et][h] = logit;
        if (h == 0) s_src[et] = s;
        atomicMax(&s_max[h], f2o(logit));
    }
    for (int base = MAXCH; base < dcount; base += MAXCH) {
        int e = base + et;
        if (e < dcount) {
            int s = g_csr_src[start + e];
            float logit = leaky(g_asrc[s * Hh + h] + s_adst[h]);
            atomicMax(&s_max[h], f2o(logit));
        }
    }
    __syncthreads();

    float m_h = o2f(s_max[h]);
    if (et < cnt0) atomicAdd(&s_den[h], expf(s_w[et][h] - m_h));
    for (int base = MAXCH; base < dcount; base += MAXCH) {
        int e = base + et;
        if (e < dcount) {
            int s = g_csr_src[start + e];
            float logit = leaky(g_asrc[s * Hh + h] + s_adst[h]);
            atomicAdd(&s_den[h], expf(logit - m_h));
        }
    }
    __syncthreads();
    if (t < Hh) {
        float eself = expf(s_self[t] - o2f(s_max[t]));
        float denom = s_den[t] + eself;
        s_den[t] = denom;
        s_wself[t] = eself / denom * (1.0f / Hh);
    }
    __syncthreads();
    if (et < cnt0)
        s_w[et][h] = expf(s_w[et][h] - m_h) / s_den[h] * (1.0f / Hh);
    __syncthreads();

    const __half* xn = g_xh + (size_t)n * HD;
    float acc = 0.f;
    #pragma unroll
    for (int hh = 0; hh < Hh; hh++)
        acc = fmaf(s_wself[hh], __half2float(xn[hh * Cc + t]), acc);

    for (int e2 = 0; e2 < cnt0; e2++) {
        const __half* xr = g_xh + (size_t)s_src[e2] * HD;
        #pragma unroll
        for (int hh = 0; hh < Hh; hh++)
            acc = fmaf(s_w[e2][hh], __half2float(xr[hh * Cc + t]), acc);
    }

    for (int base = MAXCH; base < dcount; base += MAXCH) {
        int cnt = min(MAXCH, dcount - base);
        __syncthreads();
        if (base + et < dcount) {
            int s = g_csr_src[start + base + et];
            float logit = leaky(g_asrc[s * Hh + h] + s_adst[h]);
            s_w[et][h] = expf(logit - m_h) / s_den[h] * (1.0f / Hh);
            if (h == 0) s_src[et] = s;
        }
        __syncthreads();
        for (int e2 = 0; e2 < cnt; e2++) {
            const __half* xr = g_xh + (size_t)s_src[e2] * HD;
            #pragma unroll
            for (int hh = 0; hh < Hh; hh++)
                acc = fmaf(s_w[e2][hh], __half2float(xr[hh * Cc + t]), acc);
        }
    }

    float v = acc + bias_gat[t];
    split2h(v, g_agg_hi[(size_t)n * Dm + t], g_agg_lo[(size_t)n * Dm + t]);
}

// ---------------- launch ----------------
extern "C" void kernel_launch(void* const* d_in, const int* in_sizes, int n_in,
                              void* d_out, int out_size)
{
    const float* inputs   = (const float*)d_in[0];
    const int*   eidx     = (const int*)d_in[1];
    const float* ln_gamma = (const float*)d_in[2];
    const float* ln_beta  = (const float*)d_in[3];
    const float* W1       = (const float*)d_in[4];
    const float* b1       = (const float*)d_in[5];
    const float* W_gat    = (const float*)d_in[6];
    const float* att_src  = (const float*)d_in[7];
    const float* att_dst  = (const float*)d_in[8];
    const float* bias_gat = (const float*)d_in[9];
    const float* W2       = (const float*)d_in[10];
    const float* b2       = (const float*)d_in[11];
    float*       out      = (float*)d_out;

    const int* esrc = eidx;
    const int* edst = eidx + Ee;

    __half *xln_hi, *xln_lo, *agg_hi, *agg_lo, *wg_hi, *wg_lo;
    __half *w1t, *w2, *w12, *xh;
    float *c12;
    cudaGetSymbolAddress((void**)&xln_hi, g_xln_hi);
    cudaGetSymbolAddress((void**)&xln_lo, g_xln_lo);
    cudaGetSymbolAddress((void**)&agg_hi, g_agg_hi);
    cudaGetSymbolAddress((void**)&agg_lo, g_agg_lo);
    cudaGetSymbolAddress((void**)&wg_hi, g_wg_hi);
    cudaGetSymbolAddress((void**)&wg_lo, g_wg_lo);
    cudaGetSymbolAddress((void**)&w1t, g_w1t);
    cudaGetSymbolAddress((void**)&w2,  g_w2);
    cudaGetSymbolAddress((void**)&w12, g_w12);
    cudaGetSymbolAddress((void**)&xh,  g_xh);
    cudaGetSymbolAddress((void**)&c12, g_c12);

    cudaFuncSetAttribute(gemm_mma, cudaFuncAttributeMaxDynamicSharedMemorySize, GEMM_SMEM);

    // 0: weight prep + c12 + zero init
    splitW_kernel<<<(HD * Dm) / 256, 256>>>(W1, W_gat, W2, b1);
    // 1: LayerNorm + histogram
    ln_hist_kernel<<<Nn_NODES / 8, 256>>>(inputs, ln_gamma, ln_beta, edst);
    // 2: W12 = Wgat @ W1  [1024 x 256] -> single fp16 (16 CTAs)
    gemm_mma<<<dim3(Dm / 128, HD / 128), 256, GEMM_SMEM>>>(
        wg_hi, wg_lo, w1t, Dm, nullptr, nullptr,
        nullptr, nullptr, nullptr, w12, nullptr, nullptr);
    // 3: xh = xln @ W12^T + c12 -> fp16 (+ fused attention dots)  <-- ncu idx 3
    gemm_mma<<<dim3(HD / 128, Nn_NODES / 128), 256, GEMM_SMEM>>>(
        xln_hi, xln_lo, w12, HD, c12, nullptr,
        nullptr, nullptr, nullptr, xh, att_src, att_dst);
    // 4: scan
    scan_kernel<<<1, 1024>>>();
    // 5: scatter
    scatter_kernel<<<Ee / 256, 256>>>(esrc, edst);
    // 6: fused segment softmax + aggregation -> agg (fp16 hi/lo)
    node_agg_kernel<<<Nn_NODES, 256>>>(bias_gat);
    // 7: out = agg @ W2^T + b2 + inputs
    gemm_mma<<<dim3(Dm / 128, Nn_NODES / 128), 256, GEMM_SMEM>>>(
        agg_hi, agg_lo, w2, Dm, b2, inputs,
        out, nullptr, nullptr, nullptr, nullptr, nullptr);
}

// round 15
// speedup vs baseline: 1.2106x; 1.2106x over previous
#include <cuda_runtime.h>
#include <cuda_fp16.h>
#include <cstdint>

// ---------------- problem constants ----------------
#define Nn_NODES 16384      // B*L
#define Dm 256              // d_model
#define Hh 4                // heads
#define Cc 256              // per-head channels
#define HD (Hh*Cc)          // 1024
#define Ee 65536            // edges
#define NEG_SLOPE 0.2f
#define LN_EPS 1e-6f

// ---------------- device scratch ----------------
// A-side operands: fp16 hi/lo split. B-side operands: single fp16.
__device__ __half g_xln_hi[Nn_NODES * Dm];
__device__ __half g_xln_lo[Nn_NODES * Dm];
__device__ __half g_agg_hi[Nn_NODES * Dm];
__device__ __half g_agg_lo[Nn_NODES * Dm];
__device__ __half g_wg_hi[HD * Dm], g_wg_lo[HD * Dm];   // Wgat (A of w12 GEMM)
__device__ __half g_w1t [Dm * Dm];                      // W1^T (B, single)
__device__ __half g_w2  [Dm * Dm];                      // W2   (B, single)
__device__ __half g_w12 [HD * Dm];                      // Wgat@W1 (B, single)
__device__ float  g_c12 [HD];                           // Wgat @ b1
__device__ __half g_xh  [Nn_NODES * HD];                // fp16 (halved gather traffic)
__device__ float  g_asrc[Nn_NODES * Hh];
__device__ float  g_adst[Nn_NODES * Hh];
// CSR structures
__device__ int g_deg   [Nn_NODES];
__device__ int g_offs  [Nn_NODES];
__device__ int g_cursor[Nn_NODES];
__device__ int g_csr_src[Ee];

// ---------------- helpers ----------------
__device__ __forceinline__ float leaky(float x) { return x > 0.0f ? x : NEG_SLOPE * x; }
__device__ __forceinline__ unsigned f2o(float f) {
    unsigned u = __float_as_uint(f);
    return (u & 0x80000000u) ? ~u : (u | 0x80000000u);
}
__device__ __forceinline__ float o2f(unsigned u) {
    return (u & 0x80000000u) ? __uint_as_float(u & 0x7FFFFFFFu) : __uint_as_float(~u);
}
__device__ __forceinline__ float warp_sum(float v) {
    #pragma unroll
    for (int o = 16; o > 0; o >>= 1) v += __shfl_xor_sync(0xFFFFFFFFu, v, o);
    return v;
}
__device__ __forceinline__ void split2h(float v, __half& h, __half& l) {
    h = __float2half(v);
    l = __float2half(v - __half2float(h));
}
// packed hi/lo split for a pair of floats -> two __half2 values
__device__ __forceinline__ void split2h2(float a, float b, __half2& h2, __half2& l2) {
    __half ha = __float2half(a), hb = __float2half(b);
    h2 = __halves2half2(ha, hb);
    l2 = __halves2half2(__float2half(a - __half2float(ha)),
                        __float2half(b - __half2float(hb)));
}
__device__ __forceinline__ uint32_t smem_to_u32(const void* p) {
    uint32_t a;
    asm("{ .reg .u64 t; cvta.to.shared.u64 t, %1; cvt.u32.u64 %0, t; }"
        : "=r"(a) : "l"(p));
    return a;
}

// ---------------- mma / ldmatrix / cp.async PTX (sm_80-compatible) --------
#define LDM4(r, addr) \
    asm volatile("ldmatrix.sync.aligned.m8n8.x4.shared.b16 {%0,%1,%2,%3}, [%4];" \
        : "=r"((r)[0]), "=r"((r)[1]), "=r"((r)[2]), "=r"((r)[3]) : "r"(addr))

#define MMA_F16(c, a, b0, b1) \
    asm volatile("mma.sync.aligned.m16n8k16.row.col.f32.f16.f16.f32 " \
        "{%0,%1,%2,%3}, {%4,%5,%6,%7}, {%8,%9}, {%0,%1,%2,%3};" \
        : "+f"((c)[0]), "+f"((c)[1]), "+f"((c)[2]), "+f"((c)[3]) \
        : "r"((a)[0]), "r"((a)[1]), "r"((a)[2]), "r"((a)[3]), "r"(b0), "r"(b1))

#define CP_ASYNC16(dst, src) \
    asm volatile("cp.async.cg.shared.global [%0], [%1], 16;" \
        :: "r"(dst), "l"(src) : "memory")
#define CP_COMMIT() asm volatile("cp.async.commit_group;" ::: "memory")
#define CP_WAIT1()  asm volatile("cp.async.wait_group 1;" ::: "memory")
#define CP_WAIT0()  asm volatile("cp.async.wait_group 0;" ::: "memory")

// ---------------- K0: weight prep + c12 + zero init ----------------
__global__ __launch_bounds__(256) void splitW_kernel(
    const float* __restrict__ W1, const float* __restrict__ Wg,
    const float* __restrict__ W2, const float* __restrict__ b1)
{
    int i = blockIdx.x * 256 + threadIdx.x;     // grid covers HD*Dm = 262144
    if (i < Dm * Dm) {
        int k = i >> 8, n = i & 255;
        g_w1t[n * 256 + k] = __float2half(W1[i]);   // transposed, single fp16
        g_w2[i] = __float2half(W2[i]);
    }
    split2h(Wg[i], g_wg_hi[i], g_wg_lo[i]);
    if (i < Nn_NODES) { g_deg[i] = 0; g_cursor[i] = 0; }
    if (i < Nn_NODES * Hh) { g_asrc[i] = 0.f; g_adst[i] = 0.f; }

    // c12 = Wgat @ b1 : first 128 blocks, one warp per output row
    if (blockIdx.x < 128) {
        int w = threadIdx.x >> 5, lane = threadIdx.x & 31;
        int j = blockIdx.x * 8 + w;
        float acc = 0.f;
        #pragma unroll
        for (int c = 0; c < 8; c++)
            acc = fmaf(Wg[(size_t)j * 256 + lane + c * 32], b1[lane + c * 32], acc);
        acc = warp_sum(acc);
        if (lane == 0) g_c12[j] = acc;
    }
}

// ---------------- K1: LayerNorm (warp/row) + edge histogram (fused) -------
__global__ __launch_bounds__(256) void ln_hist_kernel(
    const float* __restrict__ x, const float* __restrict__ gamma,
    const float* __restrict__ beta, const int* __restrict__ edst)
{
    if (blockIdx.x < Ee / 256) {
        int e = blockIdx.x * 256 + threadIdx.x;
        atomicAdd(&g_deg[edst[e]], 1);
    }

    int row  = blockIdx.x * 8 + (threadIdx.x >> 5);
    int lane = threadIdx.x & 31;
    const float* xr = x + (size_t)row * Dm;
    float4 v0 = *(const float4*)(xr + lane * 4);
    float4 v1 = *(const float4*)(xr + 128 + lane * 4);
    float s  = v0.x + v0.y + v0.z + v0.w + v1.x + v1.y + v1.z + v1.w;
    float s2 = v0.x*v0.x + v0.y*v0.y + v0.z*v0.z + v0.w*v0.w
             + v1.x*v1.x + v1.y*v1.y + v1.z*v1.z + v1.w*v1.w;
    s = warp_sum(s);
    s2 = warp_sum(s2);
    float mu   = s * (1.0f / Dm);
    float var  = s2 * (1.0f / Dm) - mu * mu;
    float rstd = rsqrtf(var + LN_EPS);

    float o[8];
    float4 gm0 = *(const float4*)(gamma + lane * 4);
    float4 gm1 = *(const float4*)(gamma + 128 + lane * 4);
    float4 bt0 = *(const float4*)(beta + lane * 4);
    float4 bt1 = *(const float4*)(beta + 128 + lane * 4);
    o[0] = (v0.x - mu) * rstd * gm0.x + bt0.x;
    o[1] = (v0.y - mu) * rstd * gm0.y + bt0.y;
    o[2] = (v0.z - mu) * rstd * gm0.z + bt0.z;
    o[3] = (v0.w - mu) * rstd * gm0.w + bt0.w;
    o[4] = (v1.x - mu) * rstd * gm1.x + bt1.x;
    o[5] = (v1.y - mu) * rstd * gm1.y + bt1.y;
    o[6] = (v1.z - mu) * rstd * gm1.z + bt1.z;
    o[7] = (v1.w - mu) * rstd * gm1.w + bt1.w;
    // packed half2 writes (4B per pair)
    #pragma unroll
    for (int i = 0; i < 8; i += 2) {
        size_t base = (size_t)row * Dm + (i < 4 ? lane * 4 + i : 128 + lane * 4 + i - 4);
        __half2 h2, l2;
        split2h2(o[i], o[i + 1], h2, l2);
        *(__half2*)(g_xln_hi + base) = h2;
        *(__half2*)(g_xln_lo + base) = l2;
    }
}

// ---------------- fp16x2 HMMA GEMM: C = (Ahi+Alo) @ B^T, 2 passes ---------
#define ST_STRIDE 32768
#define O_B 16384
#define GEMM_SMEM (3 * ST_STRIDE)

__global__ __launch_bounds__(256, 2) void gemm_mma(
    const __half* __restrict__ Ahi, const __half* __restrict__ Alo,
    const __half* __restrict__ B,
    int Ncols, const float* __restrict__ c_bias, const float* __restrict__ resid,
    float* __restrict__ Cf32,
    __half* __restrict__ Chi, __half* __restrict__ Clo,   // A-split output
    __half* __restrict__ Cone,                            // single-fp16 output
    const float* __restrict__ att_s, const float* __restrict__ att_d)
{
    extern __shared__ char smem[];
    uint32_t sb = smem_to_u32(smem);
    const int tid = threadIdx.x, lane = tid & 31, wid = tid >> 5;
    const int warp_m0 = (wid >> 2) * 64;
    const int warp_n0 = (wid & 3) * 32;
    const size_t m0 = (size_t)blockIdx.y * 128;
    const size_t n0 = (size_t)blockIdx.x * 128;

    float acc[4][4][4];
    #pragma unroll
    for (int i = 0; i < 4; i++)
        #pragma unroll
        for (int j = 0; j < 4; j++)
            #pragma unroll
            for (int k = 0; k < 4; k++) acc[i][j][k] = 0.f;

    const int arow = lane & 15;
    const int akb  = (lane >> 4) << 4;
    const int brl  = ((lane >> 4) << 3) | (lane & 7);
    const int bkb  = ((lane >> 3) & 1) << 4;
    const uint32_t aswz = (uint32_t)(arow & 7) << 4;
    const uint32_t bswz = (uint32_t)(lane & 7) << 4;

    auto issue = [&](int stage, int chunk) {
        int p   = chunk >> 2;                    // 0: Ahi, 1: Alo
        int kc0 = (chunk & 3) * 64;
        const __half* Ap = p ? Alo : Ahi;
        uint32_t s0 = sb + stage * ST_STRIDE;
        #pragma unroll
        for (int it = 0; it < 4; ++it) {
            int idx = tid + it * 256;
            int row = idx >> 3, c16 = idx & 7;
            uint32_t off = (uint32_t)row * 128 + c16 * 16;
            off ^= ((uint32_t)(row & 7)) << 4;           // SW128
            CP_ASYNC16(s0 + off,       Ap + (m0 + row) * 256 + kc0 + c16 * 8);
            CP_ASYNC16(s0 + O_B + off, B  + (n0 + row) * 256 + kc0 + c16 * 8);
        }
    };

    auto ldfrag = [&](uint32_t st, int k16, uint32_t af[4][4], uint32_t bf[2][4]) {
        int kbyte = k16 * 32;
        #pragma unroll
        for (int mt = 0; mt < 4; ++mt) {
            uint32_t ad = st +
                (uint32_t)(warp_m0 + mt * 16 + arow) * 128 + kbyte + akb;
            LDM4(af[mt], ad ^ aswz);
        }
        #pragma unroll
        for (int g2 = 0; g2 < 2; ++g2) {
            uint32_t bd = st + O_B +
                (uint32_t)(warp_n0 + g2 * 16 + brl) * 128 + kbyte + bkb;
            LDM4(bf[g2], bd ^ bswz);
        }
    };

    issue(0, 0); CP_COMMIT();
    issue(1, 1); CP_COMMIT();

    uint32_t af[2][4][4], bf[2][2][4];

    for (int c = 0; c < 8; ++c) {
        if (c < 7) { CP_WAIT1(); } else { CP_WAIT0(); }
        __syncthreads();
        if (c + 2 < 8) { issue((c + 2) % 3, c + 2); CP_COMMIT(); }

        uint32_t st = sb + (c % 3) * ST_STRIDE;
        ldfrag(st, 0, af[0], bf[0]);
        #pragma unroll
        for (int k16 = 0; k16 < 4; ++k16) {
            int cur = k16 & 1, nxt = cur ^ 1;
            if (k16 < 3) ldfrag(st, k16 + 1, af[nxt], bf[nxt]);
            #pragma unroll
            for (int mt = 0; mt < 4; ++mt)
                #pragma unroll
                for (int nt = 0; nt < 4; ++nt) {
                    int g2 = nt >> 1, p2 = (nt & 1) << 1;
                    MMA_F16(acc[mt][nt], af[cur][mt], bf[cur][g2][p2],
                            bf[cur][g2][p2 + 1]);
                }
        }
    }
    __syncthreads();

    // ---- epilogue ----
    const int g = lane >> 2, tq = lane & 3;

    const int h_att = (int)(n0 >> 8);
    float as0[4], as1[4], ad0[4], ad1[4];
    float ps[4][2], pd[4][2];
    if (att_s) {
        int cih0 = (int)(n0 & 255) + warp_n0 + tq * 2;
        #pragma unroll
        for (int nt = 0; nt < 4; ++nt) {
            int cih = cih0 + nt * 8;
            as0[nt] = att_s[h_att * Cc + cih];
            as1[nt] = att_s[h_att * Cc + cih + 1];
            ad0[nt] = att_d[h_att * Cc + cih];
            ad1[nt] = att_d[h_att * Cc + cih + 1];
        }
        #pragma unroll
        for (int mt = 0; mt < 4; ++mt)
            #pragma unroll
            for (int rh = 0; rh < 2; ++rh) { ps[mt][rh] = 0.f; pd[mt][rh] = 0.f; }
    }

    #pragma unroll
    for (int mt = 0; mt < 4; ++mt) {
        #pragma unroll
        for (int nt = 0; nt < 4; ++nt) {
            size_t r = m0 + warp_m0 + mt * 16 + g;
            size_t c = n0 + warp_n0 + nt * 8 + tq * 2;
            float v00 = acc[mt][nt][0], v01 = acc[mt][nt][1];
            float v10 = acc[mt][nt][2], v11 = acc[mt][nt][3];
            if (c_bias) {
                float cb0 = c_bias[c], cb1 = c_bias[c + 1];
                v00 += cb0; v01 += cb1; v10 += cb0; v11 += cb1;
            }
            size_t o0 = r * (size_t)Ncols + c;
            size_t o1 = (r + 8) * (size_t)Ncols + c;
            if (resid) {
                v00 += resid[o0]; v01 += resid[o0 + 1];
                v10 += resid[o1]; v11 += resid[o1 + 1];
            }
            if (att_s) {
                ps[mt][0] = fmaf(v00, as0[nt], fmaf(v01, as1[nt], ps[mt][0]));
                pd[mt][0] = fmaf(v00, ad0[nt], fmaf(v01, ad1[nt], pd[mt][0]));
                ps[mt][1] = fmaf(v10, as0[nt], fmaf(v11, as1[nt], ps[mt][1]));
                pd[mt][1] = fmaf(v10, ad0[nt], fmaf(v11, ad1[nt], pd[mt][1]));
            }
            if (Cf32) {
                *(float2*)(Cf32 + o0) = make_float2(v00, v01);
                *(float2*)(Cf32 + o1) = make_float2(v10, v11);
            }
            if (Chi) {
                __half2 h2, l2;
                split2h2(v00, v01, h2, l2);
                *(__half2*)(Chi + o0) = h2;
                *(__half2*)(Clo + o0) = l2;
                split2h2(v10, v11, h2, l2);
                *(__half2*)(Chi + o1) = h2;
                *(__half2*)(Clo + o1) = l2;
            }
            if (Cone) {
                *(__half2*)(Cone + o0) = __floats2half2_rn(v00, v01);
                *(__half2*)(Cone + o1) = __floats2half2_rn(v10, v11);
            }
        }
    }

    if (att_s) {
        #pragma unroll
        for (int mt = 0; mt < 4; ++mt)
            #pragma unroll
            for (int rh = 0; rh < 2; ++rh) {
                float vs = ps[mt][rh], vd = pd[mt][rh];
                vs += __shfl_xor_sync(0xFFFFFFFFu, vs, 1);
                vs += __shfl_xor_sync(0xFFFFFFFFu, vs, 2);
                vd += __shfl_xor_sync(0xFFFFFFFFu, vd, 1);
                vd += __shfl_xor_sync(0xFFFFFFFFu, vd, 2);
                if (tq == 0) {
                    size_t r = m0 + warp_m0 + mt * 16 + g + rh * 8;
                    atomicAdd(&g_asrc[r * Hh + h_att], vs);
                    atomicAdd(&g_adst[r * Hh + h_att], vd);
                }
            }
    }
}

// ---------------- scan: 1 block, int4 vectorized ----------------
__global__ __launch_bounds__(1024) void scan_kernel() {
    __shared__ int sh[2][1024];
    int t = threadIdx.x;
    const int4* d4 = (const int4*)g_deg;
    int4 v4[4];
    #pragma unroll
    for (int i = 0; i < 4; i++) v4[i] = d4[t * 4 + i];
    int v[16];
    #pragma unroll
    for (int i = 0; i < 4; i++) {
        v[i*4+0] = ((const int*)&v4[i])[0];
        v[i*4+1] = ((const int*)&v4[i])[1];
        v[i*4+2] = ((const int*)&v4[i])[2];
        v[i*4+3] = ((const int*)&v4[i])[3];
    }
    int sum = 0;
    #pragma unroll
    for (int i = 0; i < 16; i++) sum += v[i];
    sh[0][t] = sum;
    __syncthreads();
    int p = 0;
    #pragma unroll
    for (int off = 1; off < 1024; off <<= 1) {
        int val = sh[p][t] + ((t >= off) ? sh[p][t - off] : 0);
        sh[p ^ 1][t] = val;
        p ^= 1;
        __syncthreads();
    }
    int run = sh[p][t] - sum;
    int4 o4[4];
    #pragma unroll
    for (int i = 0; i < 4; i++) {
        ((int*)&o4[i])[0] = run; run += v[i*4+0];
        ((int*)&o4[i])[1] = run; run += v[i*4+1];
        ((int*)&o4[i])[2] = run; run += v[i*4+2];
        ((int*)&o4[i])[3] = run; run += v[i*4+3];
    }
    int4* out4 = (int4*)g_offs;
    #pragma unroll
    for (int i = 0; i < 4; i++) out4[t * 4 + i] = o4[i];
}

__global__ __launch_bounds__(256) void scatter_kernel(
    const int* __restrict__ esrc, const int* __restrict__ edst)
{
    int e = blockIdx.x * 256 + threadIdx.x;
    int d = edst[e];
    int pos = g_offs[d] + atomicAdd(&g_cursor[d], 1);
    g_csr_src[pos] = esrc[e];
}

// ---------------- fused node softmax + aggregation (fp16 xh gathers) -----
#define MAXCH 64
__global__ __launch_bounds__(256) void node_agg_kernel(
    const float* __restrict__ bias_gat)
{
    int n = blockIdx.x, t = threadIdx.x;
    int start = g_offs[n], dcount = g_deg[n];

    __shared__ unsigned s_max[Hh];
    __shared__ float s_den[Hh];
    __shared__ float s_adst[Hh], s_self[Hh], s_wself[Hh];
    __shared__ float s_w[MAXCH][Hh];
    __shared__ int s_src[MAXCH];

    if (t < Hh) {
        float as = g_asrc[n * Hh + t], ad = g_adst[n * Hh + t];
        s_adst[t] = ad;
        float self = leaky(as + ad);
        s_self[t] = self;
        s_max[t] = f2o(self);
        s_den[t] = 0.f;
    }
    __syncthreads();

    int et = t >> 2, h = t & 3;
    int cnt0 = min(dcount, MAXCH);

    if (et < cnt0) {
        int s = g_csr_src[start + et];
        float logit = leaky(g_asrc[s * Hh + h] + s_adst[h]);
        s_w[et][h] = logit;
        if (h == 0) s_src[et] = s;
        atomicMax(&s_max[h], f2o(logit));
    }
    for (int base = MAXCH; base < dcount; base += MAXCH) {
        int e = base + et;
        if (e < dcount) {
            int s = g_csr_src[start + e];
            float logit = leaky(g_asrc[s * Hh + h] + s_adst[h]);
            atomicMax(&s_max[h], f2o(logit));
        }
    }
    __syncthreads();

    float m_h = o2f(s_max[h]);
    if (et < cnt0) atomicAdd(&s_den[h], expf(s_w[et][h] - m_h));
    for (int base = MAXCH; base < dcount; base += MAXCH) {
        int e = base + et;
        if (e < dcount) {
            int s = g_csr_src[start + e];
            float logit = leaky(g_asrc[s * Hh + h] + s_adst[h]);
            atomicAdd(&s_den[h], expf(logit - m_h));
        }
    }
    __syncthreads();
    if (t < Hh) {
        float eself = expf(s_self[t] - o2f(s_max[t]));
        float denom = s_den[t] + eself;
        s_den[t] = denom;
        s_wself[t] = eself / denom * (1.0f / Hh);
    }
    __syncthreads();
    if (et < cnt0)
        s_w[et][h] = expf(s_w[et][h] - m_h) / s_den[h] * (1.0f / Hh);
    __syncthreads();

    const __half* xn = g_xh + (size_t)n * HD;
    float acc = 0.f;
    #pragma unroll
    for (int hh = 0; hh < Hh; hh++)
        acc = fmaf(s_wself[hh], __half2float(xn[hh * Cc + t]), acc);

    for (int e2 = 0; e2 < cnt0; e2++) {
        const __half* xr = g_xh + (size_t)s_src[e2] * HD;
        #pragma unroll
        for (int hh = 0; hh < Hh; hh++)
            acc = fmaf(s_w[e2][hh], __half2float(xr[hh * Cc + t]), acc);
    }

    for (int base = MAXCH; base < dcount; base += MAXCH) {
        int cnt = min(MAXCH, dcount - base);
        __syncthreads();
        if (base + et < dcount) {
            int s = g_csr_src[start + base + et];
            float logit = leaky(g_asrc[s * Hh + h] + s_adst[h]);
            s_w[et][h] = expf(logit - m_h) / s_den[h] * (1.0f / Hh);
            if (h == 0) s_src[et] = s;
        }
        __syncthreads();
        for (int e2 = 0; e2 < cnt; e2++) {
            const __half* xr = g_xh + (size_t)s_src[e2] * HD;
            #pragma unroll
            for (int hh = 0; hh < Hh; hh++)
                acc = fmaf(s_w[e2][hh], __half2float(xr[hh * Cc + t]), acc);
        }
    }

    float v = acc + bias_gat[t];
    split2h(v, g_agg_hi[(size_t)n * Dm + t], g_agg_lo[(size_t)n * Dm + t]);
}

// ---------------- launch ----------------
extern "C" void kernel_launch(void* const* d_in, const int* in_sizes, int n_in,
                              void* d_out, int out_size)
{
    const float* inputs   = (const float*)d_in[0];
    const int*   eidx     = (const int*)d_in[1];
    const float* ln_gamma = (const float*)d_in[2];
    const float* ln_beta  = (const float*)d_in[3];
    const float* W1       = (const float*)d_in[4];
    const float* b1       = (const float*)d_in[5];
    const float* W_gat    = (const float*)d_in[6];
    const float* att_src  = (const float*)d_in[7];
    const float* att_dst  = (const float*)d_in[8];
    const float* bias_gat = (const float*)d_in[9];
    const float* W2       = (const float*)d_in[10];
    const float* b2       = (const float*)d_in[11];
    float*       out      = (float*)d_out;

    const int* esrc = eidx;
    const int* edst = eidx + Ee;

    __half *xln_hi, *xln_lo, *agg_hi, *agg_lo, *wg_hi, *wg_lo;
    __half *w1t, *w2, *w12, *xh;
    float *c12;
    cudaGetSymbolAddress((void**)&xln_hi, g_xln_hi);
    cudaGetSymbolAddress((void**)&xln_lo, g_xln_lo);
    cudaGetSymbolAddress((void**)&agg_hi, g_agg_hi);
    cudaGetSymbolAddress((void**)&agg_lo, g_agg_lo);
    cudaGetSymbolAddress((void**)&wg_hi, g_wg_hi);
    cudaGetSymbolAddress((void**)&wg_lo, g_wg_lo);
    cudaGetSymbolAddress((void**)&w1t, g_w1t);
    cudaGetSymbolAddress((void**)&w2,  g_w2);
    cudaGetSymbolAddress((void**)&w12, g_w12);
    cudaGetSymbolAddress((void**)&xh,  g_xh);
    cudaGetSymbolAddress((void**)&c12, g_c12);

    cudaFuncSetAttribute(gemm_mma, cudaFuncAttributeMaxDynamicSharedMemorySize, GEMM_SMEM);

    // 0: weight prep + c12 + zero init
    splitW_kernel<<<(HD * Dm) / 256, 256>>>(W1, W_gat, W2, b1);
    // 1: LayerNorm + histogram
    ln_hist_kernel<<<Nn_NODES / 8, 256>>>(inputs, ln_gamma, ln_beta, edst);
    // 2: W12 = Wgat @ W1  [1024 x 256] -> single fp16 (16 CTAs)
    gemm_mma<<<dim3(Dm / 128, HD / 128), 256, GEMM_SMEM>>>(
        wg_hi, wg_lo, w1t, Dm, nullptr, nullptr,
        nullptr, nullptr, nullptr, w12, nullptr, nullptr);
    // 3: xh = xln @ W12^T + c12 -> fp16, half2 stores (+ fused att dots)
    gemm_mma<<<dim3(HD / 128, Nn_NODES / 128), 256, GEMM_SMEM>>>(
        xln_hi, xln_lo, w12, HD, c12, nullptr,
        nullptr, nullptr, nullptr, xh, att_src, att_dst);
    // 4: scan
    scan_kernel<<<1, 1024>>>();
    // 5: scatter
    scatter_kernel<<<Ee / 256, 256>>>(esrc, edst);
    // 6: fused segment softmax + aggregation -> agg (fp16 hi/lo)
    node_agg_kernel<<<Nn_NODES, 256>>>(bias_gat);
    // 7: out = agg @ W2^T + b2 + inputs
    gemm_mma<<<dim3(Dm / 128, Nn_NODES / 128), 256, GEMM_SMEM>>>(
        agg_hi, agg_lo, w2, Dm, b2, inputs,
        out, nullptr, nullptr, nullptr, nullptr, nullptr);
}

// round 16
// speedup vs baseline: 1.5168x; 1.2530x over previous
#include <cuda_runtime.h>
#include <cuda_fp16.h>
#include <cstdint>

// ---------------- problem constants ----------------
#define Nn_NODES 16384      // B*L
#define Dm 256              // d_model
#define Hh 4                // heads
#define Cc 256              // per-head channels
#define HD (Hh*Cc)          // 1024
#define Ee 65536            // edges
#define NEG_SLOPE 0.2f
#define LN_EPS 1e-6f

// ---------------- device scratch (all GEMM operands single fp16) ----------
__device__ __half g_xln [Nn_NODES * Dm];
__device__ __half g_agg [Nn_NODES * Dm];
__device__ __half g_wg  [HD * Dm];        // Wgat (A of w12 GEMM)
__device__ __half g_w1t [Dm * Dm];        // W1^T
__device__ __half g_w2  [Dm * Dm];        // W2
__device__ __half g_w12 [HD * Dm];        // Wgat@W1
__device__ float  g_c12 [HD];             // Wgat @ b1
__device__ __half g_xh  [Nn_NODES * HD];
__device__ float  g_asrc[Nn_NODES * Hh];
__device__ float  g_adst[Nn_NODES * Hh];
// CSR structures
__device__ int g_deg   [Nn_NODES];
__device__ int g_offs  [Nn_NODES];
__device__ int g_cursor[Nn_NODES];
__device__ int g_csr_src[Ee];

// ---------------- helpers ----------------
__device__ __forceinline__ float leaky(float x) { return x > 0.0f ? x : NEG_SLOPE * x; }
__device__ __forceinline__ unsigned f2o(float f) {
    unsigned u = __float_as_uint(f);
    return (u & 0x80000000u) ? ~u : (u | 0x80000000u);
}
__device__ __forceinline__ float o2f(unsigned u) {
    return (u & 0x80000000u) ? __uint_as_float(u & 0x7FFFFFFFu) : __uint_as_float(~u);
}
__device__ __forceinline__ float warp_sum(float v) {
    #pragma unroll
    for (int o = 16; o > 0; o >>= 1) v += __shfl_xor_sync(0xFFFFFFFFu, v, o);
    return v;
}
__device__ __forceinline__ uint32_t smem_to_u32(const void* p) {
    uint32_t a;
    asm("{ .reg .u64 t; cvta.to.shared.u64 t, %1; cvt.u32.u64 %0, t; }"
        : "=r"(a) : "l"(p));
    return a;
}

// ---------------- mma / ldmatrix / cp.async PTX (sm_80-compatible) --------
#define LDM4(r, addr) \
    asm volatile("ldmatrix.sync.aligned.m8n8.x4.shared.b16 {%0,%1,%2,%3}, [%4];" \
        : "=r"((r)[0]), "=r"((r)[1]), "=r"((r)[2]), "=r"((r)[3]) : "r"(addr))

#define MMA_F16(c, a, b0, b1) \
    asm volatile("mma.sync.aligned.m16n8k16.row.col.f32.f16.f16.f32 " \
        "{%0,%1,%2,%3}, {%4,%5,%6,%7}, {%8,%9}, {%0,%1,%2,%3};" \
        : "+f"((c)[0]), "+f"((c)[1]), "+f"((c)[2]), "+f"((c)[3]) \
        : "r"((a)[0]), "r"((a)[1]), "r"((a)[2]), "r"((a)[3]), "r"(b0), "r"(b1))

#define CP_ASYNC16(dst, src) \
    asm volatile("cp.async.cg.shared.global [%0], [%1], 16;" \
        :: "r"(dst), "l"(src) : "memory")
#define CP_COMMIT() asm volatile("cp.async.commit_group;" ::: "memory")
#define CP_WAIT1()  asm volatile("cp.async.wait_group 1;" ::: "memory")
#define CP_WAIT0()  asm volatile("cp.async.wait_group 0;" ::: "memory")

// ---------------- K0: weight prep + c12 + zero init ----------------
__global__ __launch_bounds__(256) void splitW_kernel(
    const float* __restrict__ W1, const float* __restrict__ Wg,
    const float* __restrict__ W2, const float* __restrict__ b1)
{
    int i = blockIdx.x * 256 + threadIdx.x;     // grid covers HD*Dm = 262144
    if (i < Dm * Dm) {
        int k = i >> 8, n = i & 255;
        g_w1t[n * 256 + k] = __float2half(W1[i]);   // transposed
        g_w2[i] = __float2half(W2[i]);
    }
    g_wg[i] = __float2half(Wg[i]);
    if (i < Nn_NODES) { g_deg[i] = 0; g_cursor[i] = 0; }
    if (i < Nn_NODES * Hh) { g_asrc[i] = 0.f; g_adst[i] = 0.f; }

    // c12 = Wgat @ b1 : first 128 blocks, one warp per output row
    if (blockIdx.x < 128) {
        int w = threadIdx.x >> 5, lane = threadIdx.x & 31;
        int j = blockIdx.x * 8 + w;
        float acc = 0.f;
        #pragma unroll
        for (int c = 0; c < 8; c++)
            acc = fmaf(Wg[(size_t)j * 256 + lane + c * 32], b1[lane + c * 32], acc);
        acc = warp_sum(acc);
        if (lane == 0) g_c12[j] = acc;
    }
}

// ---------------- K1: LayerNorm (warp/row) + edge histogram (fused) -------
__global__ __launch_bounds__(256) void ln_hist_kernel(
    const float* __restrict__ x, const float* __restrict__ gamma,
    const float* __restrict__ beta, const int* __restrict__ edst)
{
    if (blockIdx.x < Ee / 256) {
        int e = blockIdx.x * 256 + threadIdx.x;
        atomicAdd(&g_deg[edst[e]], 1);
    }

    int row  = blockIdx.x * 8 + (threadIdx.x >> 5);
    int lane = threadIdx.x & 31;
    const float* xr = x + (size_t)row * Dm;
    float4 v0 = *(const float4*)(xr + lane * 4);
    float4 v1 = *(const float4*)(xr + 128 + lane * 4);
    float s  = v0.x + v0.y + v0.z + v0.w + v1.x + v1.y + v1.z + v1.w;
    float s2 = v0.x*v0.x + v0.y*v0.y + v0.z*v0.z + v0.w*v0.w
             + v1.x*v1.x + v1.y*v1.y + v1.z*v1.z + v1.w*v1.w;
    s = warp_sum(s);
    s2 = warp_sum(s2);
    float mu   = s * (1.0f / Dm);
    float var  = s2 * (1.0f / Dm) - mu * mu;
    float rstd = rsqrtf(var + LN_EPS);

    float o[8];
    float4 gm0 = *(const float4*)(gamma + lane * 4);
    float4 gm1 = *(const float4*)(gamma + 128 + lane * 4);
    float4 bt0 = *(const float4*)(beta + lane * 4);
    float4 bt1 = *(const float4*)(beta + 128 + lane * 4);
    o[0] = (v0.x - mu) * rstd * gm0.x + bt0.x;
    o[1] = (v0.y - mu) * rstd * gm0.y + bt0.y;
    o[2] = (v0.z - mu) * rstd * gm0.z + bt0.z;
    o[3] = (v0.w - mu) * rstd * gm0.w + bt0.w;
    o[4] = (v1.x - mu) * rstd * gm1.x + bt1.x;
    o[5] = (v1.y - mu) * rstd * gm1.y + bt1.y;
    o[6] = (v1.z - mu) * rstd * gm1.z + bt1.z;
    o[7] = (v1.w - mu) * rstd * gm1.w + bt1.w;
    #pragma unroll
    for (int i = 0; i < 8; i += 2) {
        size_t base = (size_t)row * Dm + (i < 4 ? lane * 4 + i : 128 + lane * 4 + i - 4);
        *(__half2*)(g_xln + base) = __floats2half2_rn(o[i], o[i + 1]);
    }
}

// ---------------- fp16 HMMA GEMM: C = A @ B^T, single pass, K=256 ---------
#define ST_STRIDE 32768
#define O_B 16384
#define GEMM_SMEM (3 * ST_STRIDE)

__global__ __launch_bounds__(256, 2) void gemm_mma(
    const __half* __restrict__ A, const __half* __restrict__ B,
    int Ncols, const float* __restrict__ c_bias, const float* __restrict__ resid,
    float* __restrict__ Cf32, __half* __restrict__ Cone,
    const float* __restrict__ att_s, const float* __restrict__ att_d)
{
    extern __shared__ char smem[];
    uint32_t sb = smem_to_u32(smem);
    const int tid = threadIdx.x, lane = tid & 31, wid = tid >> 5;
    const int warp_m0 = (wid >> 2) * 64;
    const int warp_n0 = (wid & 3) * 32;
    const size_t m0 = (size_t)blockIdx.y * 128;
    const size_t n0 = (size_t)blockIdx.x * 128;

    float acc[4][4][4];
    #pragma unroll
    for (int i = 0; i < 4; i++)
        #pragma unroll
        for (int j = 0; j < 4; j++)
            #pragma unroll
            for (int k = 0; k < 4; k++) acc[i][j][k] = 0.f;

    const int arow = lane & 15;
    const int akb  = (lane >> 4) << 4;
    const int brl  = ((lane >> 4) << 3) | (lane & 7);
    const int bkb  = ((lane >> 3) & 1) << 4;
    const uint32_t aswz = (uint32_t)(arow & 7) << 4;
    const uint32_t bswz = (uint32_t)(lane & 7) << 4;

    auto issue = [&](int stage, int chunk) {
        int kc0 = chunk * 64;
        uint32_t s0 = sb + stage * ST_STRIDE;
        #pragma unroll
        for (int it = 0; it < 4; ++it) {
            int idx = tid + it * 256;
            int row = idx >> 3, c16 = idx & 7;
            uint32_t off = (uint32_t)row * 128 + c16 * 16;
            off ^= ((uint32_t)(row & 7)) << 4;           // SW128
            CP_ASYNC16(s0 + off,       A + (m0 + row) * 256 + kc0 + c16 * 8);
            CP_ASYNC16(s0 + O_B + off, B + (n0 + row) * 256 + kc0 + c16 * 8);
        }
    };

    auto ldfrag = [&](uint32_t st, int k16, uint32_t af[4][4], uint32_t bf[2][4]) {
        int kbyte = k16 * 32;
        #pragma unroll
        for (int mt = 0; mt < 4; ++mt) {
            uint32_t ad = st +
                (uint32_t)(warp_m0 + mt * 16 + arow) * 128 + kbyte + akb;
            LDM4(af[mt], ad ^ aswz);
        }
        #pragma unroll
        for (int g2 = 0; g2 < 2; ++g2) {
            uint32_t bd = st + O_B +
                (uint32_t)(warp_n0 + g2 * 16 + brl) * 128 + kbyte + bkb;
            LDM4(bf[g2], bd ^ bswz);
        }
    };

    issue(0, 0); CP_COMMIT();
    issue(1, 1); CP_COMMIT();

    uint32_t af[2][4][4], bf[2][2][4];

    for (int c = 0; c < 4; ++c) {
        if (c < 3) { CP_WAIT1(); } else { CP_WAIT0(); }
        __syncthreads();
        if (c + 2 < 4) { issue((c + 2) % 3, c + 2); CP_COMMIT(); }

        uint32_t st = sb + (c % 3) * ST_STRIDE;
        ldfrag(st, 0, af[0], bf[0]);
        #pragma unroll
        for (int k16 = 0; k16 < 4; ++k16) {
            int cur = k16 & 1, nxt = cur ^ 1;
            if (k16 < 3) ldfrag(st, k16 + 1, af[nxt], bf[nxt]);
            #pragma unroll
            for (int mt = 0; mt < 4; ++mt)
                #pragma unroll
                for (int nt = 0; nt < 4; ++nt) {
                    int g2 = nt >> 1, p2 = (nt & 1) << 1;
                    MMA_F16(acc[mt][nt], af[cur][mt], bf[cur][g2][p2],
                            bf[cur][g2][p2 + 1]);
                }
        }
    }
    __syncthreads();

    // ---- epilogue ----
    const int g = lane >> 2, tq = lane & 3;

    const int h_att = (int)(n0 >> 8);
    float as0[4], as1[4], ad0[4], ad1[4];
    float ps[4][2], pd[4][2];
    if (att_s) {
        int cih0 = (int)(n0 & 255) + warp_n0 + tq * 2;
        #pragma unroll
        for (int nt = 0; nt < 4; ++nt) {
            int cih = cih0 + nt * 8;
            as0[nt] = att_s[h_att * Cc + cih];
            as1[nt] = att_s[h_att * Cc + cih + 1];
            ad0[nt] = att_d[h_att * Cc + cih];
            ad1[nt] = att_d[h_att * Cc + cih + 1];
        }
        #pragma unroll
        for (int mt = 0; mt < 4; ++mt)
            #pragma unroll
            for (int rh = 0; rh < 2; ++rh) { ps[mt][rh] = 0.f; pd[mt][rh] = 0.f; }
    }

    #pragma unroll
    for (int mt = 0; mt < 4; ++mt) {
        #pragma unroll
        for (int nt = 0; nt < 4; ++nt) {
            size_t r = m0 + warp_m0 + mt * 16 + g;
            size_t c = n0 + warp_n0 + nt * 8 + tq * 2;
            float v00 = acc[mt][nt][0], v01 = acc[mt][nt][1];
            float v10 = acc[mt][nt][2], v11 = acc[mt][nt][3];
            if (c_bias) {
                float cb0 = c_bias[c], cb1 = c_bias[c + 1];
                v00 += cb0; v01 += cb1; v10 += cb0; v11 += cb1;
            }
            size_t o0 = r * (size_t)Ncols + c;
            size_t o1 = (r + 8) * (size_t)Ncols + c;
            if (resid) {
                v00 += resid[o0]; v01 += resid[o0 + 1];
                v10 += resid[o1]; v11 += resid[o1 + 1];
            }
            if (att_s) {
                ps[mt][0] = fmaf(v00, as0[nt], fmaf(v01, as1[nt], ps[mt][0]));
                pd[mt][0] = fmaf(v00, ad0[nt], fmaf(v01, ad1[nt], pd[mt][0]));
                ps[mt][1] = fmaf(v10, as0[nt], fmaf(v11, as1[nt], ps[mt][1]));
                pd[mt][1] = fmaf(v10, ad0[nt], fmaf(v11, ad1[nt], pd[mt][1]));
            }
            if (Cf32) {
                *(float2*)(Cf32 + o0) = make_float2(v00, v01);
                *(float2*)(Cf32 + o1) = make_float2(v10, v11);
            }
            if (Cone) {
                *(__half2*)(Cone + o0) = __floats2half2_rn(v00, v01);
                *(__half2*)(Cone + o1) = __floats2half2_rn(v10, v11);
            }
        }
    }

    if (att_s) {
        #pragma unroll
        for (int mt = 0; mt < 4; ++mt)
            #pragma unroll
            for (int rh = 0; rh < 2; ++rh) {
                float vs = ps[mt][rh], vd = pd[mt][rh];
                vs += __shfl_xor_sync(0xFFFFFFFFu, vs, 1);
                vs += __shfl_xor_sync(0xFFFFFFFFu, vs, 2);
                vd += __shfl_xor_sync(0xFFFFFFFFu, vd, 1);
                vd += __shfl_xor_sync(0xFFFFFFFFu, vd, 2);
                if (tq == 0) {
                    size_t r = m0 + warp_m0 + mt * 16 + g + rh * 8;
                    atomicAdd(&g_asrc[r * Hh + h_att], vs);
                    atomicAdd(&g_adst[r * Hh + h_att], vd);
                }
            }
    }
}

// ---------------- scan: 1 block, int4 vectorized ----------------
__global__ __launch_bounds__(1024) void scan_kernel() {
    __shared__ int sh[2][1024];
    int t = threadIdx.x;
    const int4* d4 = (const int4*)g_deg;
    int4 v4[4];
    #pragma unroll
    for (int i = 0; i < 4; i++) v4[i] = d4[t * 4 + i];
    int v[16];
    #pragma unroll
    for (int i = 0; i < 4; i++) {
        v[i*4+0] = ((const int*)&v4[i])[0];
        v[i*4+1] = ((const int*)&v4[i])[1];
        v[i*4+2] = ((const int*)&v4[i])[2];
        v[i*4+3] = ((const int*)&v4[i])[3];
    }
    int sum = 0;
    #pragma unroll
    for (int i = 0; i < 16; i++) sum += v[i];
    sh[0][t] = sum;
    __syncthreads();
    int p = 0;
    #pragma unroll
    for (int off = 1; off < 1024; off <<= 1) {
        int val = sh[p][t] + ((t >= off) ? sh[p][t - off] : 0);
        sh[p ^ 1][t] = val;
        p ^= 1;
        __syncthreads();
    }
    int run = sh[p][t] - sum;
    int4 o4[4];
    #pragma unroll
    for (int i = 0; i < 4; i++) {
        ((int*)&o4[i])[0] = run; run += v[i*4+0];
        ((int*)&o4[i])[1] = run; run += v[i*4+1];
        ((int*)&o4[i])[2] = run; run += v[i*4+2];
        ((int*)&o4[i])[3] = run; run += v[i*4+3];
    }
    int4* out4 = (int4*)g_offs;
    #pragma unroll
    for (int i = 0; i < 4; i++) out4[t * 4 + i] = o4[i];
}

__global__ __launch_bounds__(256) void scatter_kernel(
    const int* __restrict__ esrc, const int* __restrict__ edst)
{
    int e = blockIdx.x * 256 + threadIdx.x;
    int d = edst[e];
    int pos = g_offs[d] + atomicAdd(&g_cursor[d], 1);
    g_csr_src[pos] = esrc[e];
}

// ---------------- fused node softmax + aggregation (fp16 xh gathers) -----
#define MAXCH 64
__global__ __launch_bounds__(256) void node_agg_kernel(
    const float* __restrict__ bias_gat)
{
    int n = blockIdx.x, t = threadIdx.x;
    int start = g_offs[n], dcount = g_deg[n];

    __shared__ unsigned s_max[Hh];
    __shared__ float s_den[Hh];
    __shared__ float s_adst[Hh], s_self[Hh], s_wself[Hh];
    __shared__ float s_w[MAXCH][Hh];
    __shared__ int s_src[MAXCH];

    if (t < Hh) {
        float as = g_asrc[n * Hh + t], ad = g_adst[n * Hh + t];
        s_adst[t] = ad;
        float self = leaky(as + ad);
        s_self[t] = self;
        s_max[t] = f2o(self);
        s_den[t] = 0.f;
    }
    __syncthreads();

    int et = t >> 2, h = t & 3;
    int cnt0 = min(dcount, MAXCH);

    if (et < cnt0) {
        int s = g_csr_src[start + et];
        float logit = leaky(g_asrc[s * Hh + h] + s_adst[h]);
        s_w[et][h] = logit;
        if (h == 0) s_src[et] = s;
        atomicMax(&s_max[h], f2o(logit));
    }
    for (int base = MAXCH; base < dcount; base += MAXCH) {
        int e = base + et;
        if (e < dcount) {
            int s = g_csr_src[start + e];
            float logit = leaky(g_asrc[s * Hh + h] + s_adst[h]);
            atomicMax(&s_max[h], f2o(logit));
        }
    }
    __syncthreads();

    float m_h = o2f(s_max[h]);
    if (et < cnt0) atomicAdd(&s_den[h], expf(s_w[et][h] - m_h));
    for (int base = MAXCH; base < dcount; base += MAXCH) {
        int e = base + et;
        if (e < dcount) {
            int s = g_csr_src[start + e];
            float logit = leaky(g_asrc[s * Hh + h] + s_adst[h]);
            atomicAdd(&s_den[h], expf(logit - m_h));
        }
    }
    __syncthreads();
    if (t < Hh) {
        float eself = expf(s_self[t] - o2f(s_max[t]));
        float denom = s_den[t] + eself;
        s_den[t] = denom;
        s_wself[t] = eself / denom * (1.0f / Hh);
    }
    __syncthreads();
    if (et < cnt0)
        s_w[et][h] = expf(s_w[et][h] - m_h) / s_den[h] * (1.0f / Hh);
    __syncthreads();

    const __half* xn = g_xh + (size_t)n * HD;
    float acc = 0.f;
    #pragma unroll
    for (int hh = 0; hh < Hh; hh++)
        acc = fmaf(s_wself[hh], __half2float(xn[hh * Cc + t]), acc);

    for (int e2 = 0; e2 < cnt0; e2++) {
        const __half* xr = g_xh + (size_t)s_src[e2] * HD;
        #pragma unroll
        for (int hh = 0; hh < Hh; hh++)
            acc = fmaf(s_w[e2][hh], __half2float(xr[hh * Cc + t]), acc);
    }

    for (int base = MAXCH; base < dcount; base += MAXCH) {
        int cnt = min(MAXCH, dcount - base);
        __syncthreads();
        if (base + et < dcount) {
            int s = g_csr_src[start + base + et];
            float logit = leaky(g_asrc[s * Hh + h] + s_adst[h]);
            s_w[et][h] = expf(logit - m_h) / s_den[h] * (1.0f / Hh);
            if (h == 0) s_src[et] = s;
        }
        __syncthreads();
        for (int e2 = 0; e2 < cnt; e2++) {
            const __half* xr = g_xh + (size_t)s_src[e2] * HD;
            #pragma unroll
            for (int hh = 0; hh < Hh; hh++)
                acc = fmaf(s_w[e2][hh], __half2float(xr[hh * Cc + t]), acc);
        }
    }

    float v = acc + bias_gat[t];
    g_agg[(size_t)n * Dm + t] = __float2half(v);
}

// ---------------- launch ----------------
extern "C" void kernel_launch(void* const* d_in, const int* in_sizes, int n_in,
                              void* d_out, int out_size)
{
    const float* inputs   = (const float*)d_in[0];
    const int*   eidx     = (const int*)d_in[1];
    const float* ln_gamma = (const float*)d_in[2];
    const float* ln_beta  = (const float*)d_in[3];
    const float* W1       = (const float*)d_in[4];
    const float* b1       = (const float*)d_in[5];
    const float* W_gat    = (const float*)d_in[6];
    const float* att_src  = (const float*)d_in[7];
    const float* att_dst  = (const float*)d_in[8];
    const float* bias_gat = (const float*)d_in[9];
    const float* W2       = (const float*)d_in[10];
    const float* b2       = (const float*)d_in[11];
    float*       out      = (float*)d_out;

    const int* esrc = eidx;
    const int* edst = eidx + Ee;

    __half *xln, *agg, *wg, *w1t, *w2, *w12, *xh;
    float *c12;
    cudaGetSymbolAddress((void**)&xln, g_xln);
    cudaGetSymbolAddress((void**)&agg, g_agg);
    cudaGetSymbolAddress((void**)&wg,  g_wg);
    cudaGetSymbolAddress((void**)&w1t, g_w1t);
    cudaGetSymbolAddress((void**)&w2,  g_w2);
    cudaGetSymbolAddress((void**)&w12, g_w12);
    cudaGetSymbolAddress((void**)&xh,  g_xh);
    cudaGetSymbolAddress((void**)&c12, g_c12);

    cudaFuncSetAttribute(gemm_mma, cudaFuncAttributeMaxDynamicSharedMemorySize, GEMM_SMEM);

    // 0: weight prep + c12 + zero init
    splitW_kernel<<<(HD * Dm) / 256, 256>>>(W1, W_gat, W2, b1);
    // 1: LayerNorm + histogram
    ln_hist_kernel<<<Nn_NODES / 8, 256>>>(inputs, ln_gamma, ln_beta, edst);
    // 2: W12 = Wgat @ W1  [1024 x 256] -> fp16 (16 CTAs)
    gemm_mma<<<dim3(Dm / 128, HD / 128), 256, GEMM_SMEM>>>(
        wg, w1t, Dm, nullptr, nullptr, nullptr, w12, nullptr, nullptr);
    // 3: xh = xln @ W12^T + c12 -> fp16 (+ fused attention dots)
    gemm_mma<<<dim3(HD / 128, Nn_NODES / 128), 256, GEMM_SMEM>>>(
        xln, w12, HD, c12, nullptr, nullptr, xh, att_src, att_dst);
    // 4: scan
    scan_kernel<<<1, 1024>>>();
    // 5: scatter
    scatter_kernel<<<Ee / 256, 256>>>(esrc, edst);
    // 6: fused segment softmax + aggregation -> agg (fp16)
    node_agg_kernel<<<Nn_NODES, 256>>>(bias_gat);
    // 7: out = agg @ W2^T + b2 + inputs
    gemm_mma<<<dim3(Dm / 128, Nn_NODES / 128), 256, GEMM_SMEM>>>(
        agg, w2, Dm, b2, inputs, out, nullptr, nullptr, nullptr);
}